// round 10
// baseline (speedup 1.0000x reference)
#include <cuda_runtime.h>
#include <cuda_fp16.h>
#include <cstdint>
#include <cstddef>

#define N_SRC   100000
#define N_DST   50000
#define NODE_IN 128
#define HID     64
#define NTILE   (N_DST / 8)

__device__ __half g_P[(size_t)N_SRC * HID];   // fp16 storage (12.8 MB, L2-resident)
__device__ float  g_R[(size_t)N_DST * HID];

// ---------------------------------------------------------------------------
__device__ __forceinline__ uint32_t smem_u32(const void* p) {
    uint32_t a;
    asm("{ .reg .u64 t; cvta.to.shared.u64 t, %1; cvt.u32.u64 %0, t; }" : "=r"(a) : "l"(p));
    return a;
}
__device__ __forceinline__ void ldsm4(uint32_t r[4], uint32_t addr) {
    asm volatile("ldmatrix.sync.aligned.m8n8.x4.shared.b16 {%0,%1,%2,%3}, [%4];"
        : "=r"(r[0]), "=r"(r[1]), "=r"(r[2]), "=r"(r[3]) : "r"(addr));
}
__device__ __forceinline__ void mma_f16(float d[4], const uint32_t a[4],
                                        uint32_t b0, uint32_t b1) {
    asm volatile("mma.sync.aligned.m16n8k16.row.col.f32.f16.f16.f32 "
        "{%0,%1,%2,%3}, {%4,%5,%6,%7}, {%8,%9}, {%0,%1,%2,%3};"
        : "+f"(d[0]), "+f"(d[1]), "+f"(d[2]), "+f"(d[3])
        : "r"(a[0]), "r"(a[1]), "r"(a[2]), "r"(a[3]), "r"(b0), "r"(b1));
}
__device__ __forceinline__ uint32_t h2u(__half2 v) { return *(uint32_t*)&v; }

// 1-pass fp16 GEMM (warp tile 32x32) — used by k_projT
template<int KSTEPS, int STRIDE>
__device__ __forceinline__ void gemm_1p(uint32_t aS, uint32_t bS,
                                        int mrow, int ncol, int lane,
                                        float acc[2][4][4]) {
    const int arow = mrow + (lane & 15);
    const int asel = (lane >> 4) * 8;
    const int brow = ncol + ((lane >> 4) << 3) + (lane & 7);
    const int bsel = ((lane >> 3) & 1) * 8;
    #pragma unroll
    for (int ks = 0; ks < KSTEPS; ks++) {
        uint32_t ah[2][4], bs[2][4];
        #pragma unroll
        for (int mt = 0; mt < 2; mt++) {
            const uint32_t off = (uint32_t)(((arow + mt * 16) * STRIDE + ks * 16 + asel) * 2);
            ldsm4(ah[mt], aS + off);
        }
        #pragma unroll
        for (int j = 0; j < 2; j++) {
            const uint32_t off = (uint32_t)(((brow + j * 16) * STRIDE + ks * 16 + bsel) * 2);
            ldsm4(bs[j], bS + off);
        }
        #pragma unroll
        for (int mt = 0; mt < 2; mt++)
            #pragma unroll
            for (int nt = 0; nt < 4; nt++) {
                const int j = nt >> 1, hf = (nt & 1) * 2;
                mma_f16(acc[mt][nt], ah[mt], bs[j][hf], bs[j][hf + 1]);
            }
    }
}

// ---------------------------------------------------------------------------
// Kernel 1: P(fp16) = nf @ Wo_top, R(fp32) = nf[:N_DST] @ Wn_top  (1-pass)
// ---------------------------------------------------------------------------
#define POFF_A  0        // 128 x 136 fp16 = 34816 B
#define POFF_W  34816    // 64 x 136 fp16 = 17408 B
#define PJ_SMEM 52224
#define PJ_BLOCKS 296
#define PJ_PSPLIT 197

__global__ __launch_bounds__(256, 2)
void k_projT(const float* __restrict__ nf,
             const float* __restrict__ Wo,
             const float* __restrict__ Wn)
{
    extern __shared__ char smc[];
    const int tid = threadIdx.x, lane = tid & 31, wid = tid >> 5;
    const int mrow = (wid & 3) * 32, ncol = (wid >> 2) * 32;

    const bool isP = (blockIdx.x < PJ_PSPLIT);
    const float* W = isP ? Wo : Wn;
    const int limit = isP ? N_SRC : N_DST;
    const int ntile = (limit + 127) >> 7;
    const int t0 = isP ? blockIdx.x : (blockIdx.x - PJ_PSPLIT);
    const int ts = isP ? PJ_PSPLIT : (PJ_BLOCKS - PJ_PSPLIT);

    for (int i = tid; i < 64 * 128; i += 256) {
        const int n = i >> 7, k = i & 127;
        ((__half*)(smc + POFF_W))[n * 136 + k] = __float2half(W[k * 64 + n]);
    }
    const uint32_t aS = smem_u32(smc + POFF_A);
    const uint32_t bS = smem_u32(smc + POFF_W);

    for (int tile = t0; tile < ntile; tile += ts) {
        __syncthreads();
        const int base = tile * 128;
        #pragma unroll
        for (int t = 0; t < 8; t++) {
            const int idx = tid + 256 * t;
            const int r = idx >> 4, c16 = idx & 15;
            float4 v0 = make_float4(0.f, 0.f, 0.f, 0.f), v1 = v0;
            if (base + r < limit) {
                const float4* row = (const float4*)(nf + (size_t)(base + r) * NODE_IN);
                v0 = row[c16 * 2];
                v1 = row[c16 * 2 + 1];
            }
            uint4 pk;
            pk.x = h2u(__floats2half2_rn(v0.x, v0.y));
            pk.y = h2u(__floats2half2_rn(v0.z, v0.w));
            pk.z = h2u(__floats2half2_rn(v1.x, v1.y));
            pk.w = h2u(__floats2half2_rn(v1.z, v1.w));
            *(uint4*)(smc + POFF_A + (size_t)r * 272 + c16 * 16) = pk;
        }
        __syncthreads();

        float acc[2][4][4];
        #pragma unroll
        for (int a = 0; a < 2; a++)
            #pragma unroll
            for (int b = 0; b < 4; b++)
                #pragma unroll
                for (int c = 0; c < 4; c++) acc[a][b][c] = 0.f;

        gemm_1p<8, 136>(aS, bS, mrow, ncol, lane, acc);

        #pragma unroll
        for (int mt = 0; mt < 2; mt++) {
            const int r0 = base + mrow + mt * 16 + (lane >> 2);
            #pragma unroll
            for (int nt = 0; nt < 4; nt++) {
                const int c = ncol + nt * 8 + (lane & 3) * 2;
                if (isP) {
                    if (r0 < limit)
                        *(uint32_t*)(g_P + (size_t)r0 * HID + c) =
                            h2u(__floats2half2_rn(acc[mt][nt][0], acc[mt][nt][1]));
                    if (r0 + 8 < limit)
                        *(uint32_t*)(g_P + (size_t)(r0 + 8) * HID + c) =
                            h2u(__floats2half2_rn(acc[mt][nt][2], acc[mt][nt][3]));
                } else {
                    if (r0 < limit)
                        *(float2*)(g_R + (size_t)r0 * HID + c) =
                            make_float2(acc[mt][nt][0], acc[mt][nt][1]);
                    if (r0 + 8 < limit)
                        *(float2*)(g_R + (size_t)(r0 + 8) * HID + c) =
                            make_float2(acc[mt][nt][2], acc[mt][nt][3]);
                }
            }
        }
    }
}

// ---------------------------------------------------------------------------
// Kernel 2: fused pipeline — 16x64 warp tiles, fragment chaining GEMM1->GEMM2,
//           warp-parallel shfl sparsemax, 2 syncs/tile
// ---------------------------------------------------------------------------
#define OFF_E    0        // 128 x 72 fp16 = 18432
#define OFF_W1   18432
#define OFF_W2   27648
#define OFF_W3   36864
#define OFF_HN   46080    // 16 x 72 fp16 (rows 8..15 stay zero)
#define OFF_LOG  48384    // 128 floats (final: leaky(cval + dot))
#define OFF_V    48896
#define OFF_BE   49152
#define OFF_BO   49408
#define OFF_BN   49664
#define OFF_SRC  49920
#define OFF_C    50432
#define FS_SMEM  50448

__global__ __launch_bounds__(256, 2)
void k_fusedT(const float* __restrict__ ef,
              const int*   __restrict__ src_idx,
              const float* __restrict__ We,  const float* __restrict__ be,
              const float* __restrict__ Wa,  const float* __restrict__ ba,
              const float* __restrict__ wa,
              const float* __restrict__ Wo,  const float* __restrict__ bo,
              const float* __restrict__ Wn,  const float* __restrict__ bn,
              float* __restrict__ out)
{
    extern __shared__ char smc[];
    const int tid = threadIdx.x, lane = tid & 31, wid = tid >> 5;

    float* sLog = (float*)(smc + OFF_LOG);
    float* sV   = (float*)(smc + OFF_V);
    float* sBe  = (float*)(smc + OFF_BE);
    float* sBo  = (float*)(smc + OFF_BO);
    float* sBn  = (float*)(smc + OFF_BN);
    int*   sSrc = (int*)  (smc + OFF_SRC);

    for (int i = tid; i < 4096; i += 256) {
        const int n = i >> 6, k = i & 63;
        ((__half*)(smc + OFF_W1))[n * 72 + k] = __float2half(We[k * 64 + n]);
        ((__half*)(smc + OFF_W2))[n * 72 + k] = __float2half(Wo[(NODE_IN + k) * 64 + n]);
        ((__half*)(smc + OFF_W3))[n * 72 + k] = __float2half(Wn[(NODE_IN + k) * 64 + n]);
    }
    // zero HN pad rows 8..15 (never written again)
    for (int i = tid; i < 288; i += 256)
        ((uint32_t*)(smc + OFF_HN + 1152))[i] = 0;
    if (tid < 64) {
        sBe[tid] = be[tid]; sBo[tid] = bo[tid]; sBn[tid] = bn[tid];
        float sv = 0.f;
        #pragma unroll 8
        for (int k = 0; k < 64; k++) sv = fmaf(Wa[tid * 64 + k], wa[k], sv);
        sV[tid] = sv;
    }
    if (tid == 64) {
        float sc = 0.f;
        for (int k = 0; k < 64; k++) sc = fmaf(ba[k], wa[k], sc);
        *(float*)(smc + OFF_C) = sc;
    }
    __syncthreads();
    const float cval = *(const float*)(smc + OFF_C);

    const uint32_t eS = smem_u32(smc + OFF_E);
    const uint32_t w1 = smem_u32(smc + OFF_W1), w2 = smem_u32(smc + OFF_W2);
    const uint32_t w3 = smem_u32(smc + OFF_W3);
    const uint32_t hnS = smem_u32(smc + OFF_HN);

    // warp-tile geometry: each warp owns rows wid*16..+15 (= one node), all 64 cols
    const int arow = wid * 16 + (lane & 15);
    const int asel = (lane >> 4) * 8;
    const int bro  = ((lane >> 4) << 3) + (lane & 7);
    const int bsel = ((lane >> 3) & 1) * 8;

    // hoist GEMM3 B fragments (loop-invariant): warp owns cols wid*8..+7
    uint32_t b3[2][4];
    {
        const int nc = wid * 8;
        #pragma unroll
        for (int g = 0; g < 2; g++) {
            const uint32_t off = (uint32_t)(((nc + (lane & 7)) * 72 + (lane >> 3) * 8 + g * 32) * 2);
            ldsm4(b3[g], w3 + off);
        }
    }

    for (int tile = blockIdx.x; tile < NTILE; tile += gridDim.x) {
        // ---- stage E tile -> single fp16 (uint4) + fused FINAL logits ----
        const float4* eg = (const float4*)(ef + (size_t)tile * 8192);
        #pragma unroll
        for (int t = 0; t < 4; t++) {
            const int idx = tid + 256 * t;       // 0..1023
            const int r = idx >> 3, c8 = idx & 7;
            const float4 v0 = eg[r * 16 + c8 * 2];
            const float4 v1 = eg[r * 16 + c8 * 2 + 1];
            uint4 pk;
            pk.x = h2u(__floats2half2_rn(v0.x, v0.y));
            pk.y = h2u(__floats2half2_rn(v0.z, v0.w));
            pk.z = h2u(__floats2half2_rn(v1.x, v1.y));
            pk.w = h2u(__floats2half2_rn(v1.z, v1.w));
            *(uint4*)(smc + OFF_E + (size_t)r * 144 + c8 * 16) = pk;
            const float* vv = sV + c8 * 8;
            float p = v0.x * vv[0] + v0.y * vv[1] + v0.z * vv[2] + v0.w * vv[3]
                    + v1.x * vv[4] + v1.y * vv[5] + v1.z * vv[6] + v1.w * vv[7];
            p += __shfl_xor_sync(0xffffffffu, p, 1);
            p += __shfl_xor_sync(0xffffffffu, p, 2);
            p += __shfl_xor_sync(0xffffffffu, p, 4);
            if ((tid & 7) == 0) {
                const float raw = p + cval;
                sLog[r] = (raw > 0.f) ? raw : 0.01f * raw;   // final leaky logit
            }
        }
        if (tid < 128) sSrc[tid] = src_idx[tile * 128 + tid];
        __syncthreads();   // S1: E + logits + src visible

        // ---- warp-parallel sparsemax for this warp's node (16 lanes) ----
        float tau, amax;
        {
            const int sl = lane & 15;
            const float v = sLog[wid * 16 + sl];
            float m = v;
            m = fmaxf(m, __shfl_xor_sync(0xffffffffu, m, 1));
            m = fmaxf(m, __shfl_xor_sync(0xffffffffu, m, 2));
            m = fmaxf(m, __shfl_xor_sync(0xffffffffu, m, 4));
            m = fmaxf(m, __shfl_xor_sync(0xffffffffu, m, 8));
            amax = m;
            float z = v - amax;
            // bitonic sort ascending across lanes 0..15 (upper half mirrors)
            #pragma unroll
            for (int k = 2; k <= 16; k <<= 1)
                #pragma unroll
                for (int j = k >> 1; j > 0; j >>= 1) {
                    const float o = __shfl_xor_sync(0xffffffffu, z, j);
                    const bool keepmin = ((sl & j) == 0) == ((sl & k) == 0);
                    z = keepmin ? fminf(z, o) : fmaxf(z, o);
                }
            // suffix sum cs_sl = sum_{t>=sl} z_t (valid in lower half)
            float cs = z;
            #pragma unroll
            for (int d = 1; d < 16; d <<= 1) {
                const float o = __shfl_down_sync(0xffffffffu, cs, d);
                if (sl + d < 16) cs += o;
            }
            // lane sl corresponds to descending rank j = 16 - sl
            const float jf = (float)(16 - sl);
            const bool ok = (1.f + jf * z > cs);
            float kmax = ok ? jf : 0.f;
            kmax = fmaxf(kmax, __shfl_xor_sync(0xffffffffu, kmax, 1));
            kmax = fmaxf(kmax, __shfl_xor_sync(0xffffffffu, kmax, 2));
            kmax = fmaxf(kmax, __shfl_xor_sync(0xffffffffu, kmax, 4));
            kmax = fmaxf(kmax, __shfl_xor_sync(0xffffffffu, kmax, 8));
            float sel = (ok && jf == kmax) ? cs : 0.f;
            sel += __shfl_xor_sync(0xffffffffu, sel, 1);
            sel += __shfl_xor_sync(0xffffffffu, sel, 2);
            sel += __shfl_xor_sync(0xffffffffu, sel, 4);
            sel += __shfl_xor_sync(0xffffffffu, sel, 8);
            tau = (sel - 1.f) / kmax;
            // lane 0 (lower half) is authoritative; broadcast to all 32 lanes
            tau  = __shfl_sync(0xffffffffu, tau, 0);
            amax = __shfl_sync(0xffffffffu, amax, 0);
        }

        // ---- GEMM1: acc1 = E[16 rows] @ We^T (full 64 cols) ----
        float acc1[8][4];
        #pragma unroll
        for (int b = 0; b < 8; b++)
            #pragma unroll
            for (int c = 0; c < 4; c++) acc1[b][c] = 0.f;
        #pragma unroll
        for (int ks = 0; ks < 4; ks++) {
            uint32_t a[4], bs[4][4];
            ldsm4(a, eS + (uint32_t)((arow * 72 + ks * 16 + asel) * 2));
            #pragma unroll
            for (int g = 0; g < 4; g++)
                ldsm4(bs[g], w1 + (uint32_t)(((g * 16 + bro) * 72 + ks * 16 + bsel) * 2));
            #pragma unroll
            for (int nt = 0; nt < 8; nt++)
                mma_f16(acc1[nt], a, bs[nt >> 1][(nt & 1) * 2], bs[nt >> 1][(nt & 1) * 2 + 1]);
        }

        // ---- chain: relu(+be) -> fp16 A2 fragments IN REGISTERS ----
        uint32_t a2[4][4];
        #pragma unroll
        for (int ks = 0; ks < 4; ks++)
            #pragma unroll
            for (int hlf = 0; hlf < 2; hlf++) {
                const int nt = 2 * ks + hlf;
                const int c0 = nt * 8 + (lane & 3) * 2;
                const float x0 = fmaxf(acc1[nt][0] + sBe[c0],     0.f);
                const float x1 = fmaxf(acc1[nt][1] + sBe[c0 + 1], 0.f);
                const float x2 = fmaxf(acc1[nt][2] + sBe[c0],     0.f);
                const float x3 = fmaxf(acc1[nt][3] + sBe[c0 + 1], 0.f);
                a2[ks][2 * hlf]     = h2u(__floats2half2_rn(x0, x1));
                a2[ks][2 * hlf + 1] = h2u(__floats2half2_rn(x2, x3));
            }

        // ---- GEMM2: acc = e_out @ Wo_bot^T (A from registers, no smem) ----
        float acc[8][4];
        #pragma unroll
        for (int b = 0; b < 8; b++)
            #pragma unroll
            for (int c = 0; c < 4; c++) acc[b][c] = 0.f;
        #pragma unroll
        for (int ks = 0; ks < 4; ks++) {
            uint32_t bs[4][4];
            #pragma unroll
            for (int g = 0; g < 4; g++)
                ldsm4(bs[g], w2 + (uint32_t)(((g * 16 + bro) * 72 + ks * 16 + bsel) * 2));
            #pragma unroll
            for (int nt = 0; nt < 8; nt++)
                mma_f16(acc[nt], a2[ks], bs[nt >> 1][(nt & 1) * 2], bs[nt >> 1][(nt & 1) * 2 + 1]);
        }

        // ---- epilogue2: m = relu(acc + P[src] + bo); alpha-weight; reduce
        //      over the warp's 16 edge rows -> HN row `wid` ----
        {
            const int r0 = wid * 16 + (lane >> 2);
            const int r1 = r0 + 8;
            const int s0 = sSrc[r0], s1 = sSrc[r1];
            const float at = amax + tau;
            const float al0 = fmaxf(sLog[r0] - at, 0.f);
            const float al1 = fmaxf(sLog[r1] - at, 0.f);
            #pragma unroll
            for (int nt = 0; nt < 8; nt++) {
                const int c = nt * 8 + (lane & 3) * 2;
                const uint32_t pv0 = *(const uint32_t*)(g_P + (size_t)s0 * HID + c);
                const uint32_t pv1 = *(const uint32_t*)(g_P + (size_t)s1 * HID + c);
                const float2 p0 = __half22float2(*(const __half2*)&pv0);
                const float2 p1 = __half22float2(*(const __half2*)&pv1);
                const float m00 = fmaxf(acc[nt][0] + p0.x + sBo[c],     0.f);
                const float m01 = fmaxf(acc[nt][1] + p0.y + sBo[c + 1], 0.f);
                const float m10 = fmaxf(acc[nt][2] + p1.x + sBo[c],     0.f);
                const float m11 = fmaxf(acc[nt][3] + p1.y + sBo[c + 1], 0.f);
                float sx = m00 * al0 + m10 * al1;
                float sy = m01 * al0 + m11 * al1;
                sx += __shfl_xor_sync(0xffffffffu, sx, 4);
                sy += __shfl_xor_sync(0xffffffffu, sy, 4);
                sx += __shfl_xor_sync(0xffffffffu, sx, 8);
                sy += __shfl_xor_sync(0xffffffffu, sy, 8);
                sx += __shfl_xor_sync(0xffffffffu, sx, 16);
                sy += __shfl_xor_sync(0xffffffffu, sy, 16);
                if (lane < 4)
                    *(uint32_t*)(smc + OFF_HN + (size_t)(wid * 72 + c) * 2) =
                        h2u(__floats2half2_rn(sx, sy));
            }
        }
        __syncthreads();   // S2: HN visible

        // ---- GEMM3 (M=16 padded, 1-pass): out = relu(R + HN @ Wn_bot^T + bn) ----
        {
            float acc3[4] = {0.f, 0.f, 0.f, 0.f};
            #pragma unroll
            for (int ks = 0; ks < 4; ks++) {
                uint32_t a3[4];
                const uint32_t aoff = (uint32_t)(((lane & 15) * 72 + ks * 16 + (lane >> 4) * 8) * 2);
                ldsm4(a3, hnS + aoff);
                const int g = ks >> 1, pr = (ks & 1) * 2;
                mma_f16(acc3, a3, b3[g][pr], b3[g][pr + 1]);
            }
            const int node = tile * 8 + (lane >> 2);
            const int col = wid * 8 + (lane & 3) * 2;
            const float2 r2 = *(const float2*)(g_R + (size_t)node * HID + col);
            const float o0 = acc3[0] + r2.x + sBn[col];
            const float o1 = acc3[1] + r2.y + sBn[col + 1];
            *(float2*)(out + (size_t)node * HID + col) =
                make_float2(fmaxf(o0, 0.f), fmaxf(o1, 0.f));
        }
        // no trailing sync: next-tile staging (E/sLog/sSrc writes) is ordered
        // against this tile's readers by S2 + program order; next-tile HN
        // writes are fenced behind next S1.
    }
}

// ---------------------------------------------------------------------------
extern "C" void kernel_launch(void* const* d_in, const int* in_sizes, int n_in,
                              void* d_out, int out_size)
{
    const float* nf = (const float*)d_in[0];
    const float* ef = (const float*)d_in[1];
    const int*   si = (const int*)  d_in[2];
    const float* We = (const float*)d_in[3];
    const float* be = (const float*)d_in[4];
    const float* Wa = (const float*)d_in[5];
    const float* ba = (const float*)d_in[6];
    const float* wa = (const float*)d_in[7];
    const float* Wo = (const float*)d_in[8];
    const float* bo = (const float*)d_in[9];
    const float* Wn = (const float*)d_in[10];
    const float* bn = (const float*)d_in[11];
    float* out = (float*)d_out;

    cudaFuncSetAttribute(k_projT,  cudaFuncAttributeMaxDynamicSharedMemorySize, PJ_SMEM);
    cudaFuncSetAttribute(k_fusedT, cudaFuncAttributeMaxDynamicSharedMemorySize, FS_SMEM);

    k_projT<<<PJ_BLOCKS, 256, PJ_SMEM>>>(nf, Wo, Wn);
    k_fusedT<<<296, 256, FS_SMEM>>>(ef, si, We, be, Wa, ba, wa, Wo, bo, Wn, bn, out);
}

// round 11
// speedup vs baseline: 1.0251x; 1.0251x over previous
#include <cuda_runtime.h>
#include <cuda_fp16.h>
#include <cstdint>
#include <cstddef>

#define N_SRC   100000
#define N_DST   50000
#define NODE_IN 128
#define HID     64
#define NTILE   (N_DST / 8)

__device__ __half g_P[(size_t)N_SRC * HID];   // fp16 storage (12.8 MB, L2-resident)
__device__ float  g_R[(size_t)N_DST * HID];

// ---------------------------------------------------------------------------
__device__ __forceinline__ uint32_t smem_u32(const void* p) {
    uint32_t a;
    asm("{ .reg .u64 t; cvta.to.shared.u64 t, %1; cvt.u32.u64 %0, t; }" : "=r"(a) : "l"(p));
    return a;
}
__device__ __forceinline__ void ldsm4(uint32_t r[4], uint32_t addr) {
    asm volatile("ldmatrix.sync.aligned.m8n8.x4.shared.b16 {%0,%1,%2,%3}, [%4];"
        : "=r"(r[0]), "=r"(r[1]), "=r"(r[2]), "=r"(r[3]) : "r"(addr));
}
__device__ __forceinline__ void stsm4(uint32_t addr, uint32_t r0, uint32_t r1,
                                      uint32_t r2, uint32_t r3) {
    asm volatile("stmatrix.sync.aligned.m8n8.x4.shared.b16 [%0], {%1,%2,%3,%4};"
        :: "r"(addr), "r"(r0), "r"(r1), "r"(r2), "r"(r3) : "memory");
}
__device__ __forceinline__ void mma_f16(float d[4], const uint32_t a[4],
                                        uint32_t b0, uint32_t b1) {
    asm volatile("mma.sync.aligned.m16n8k16.row.col.f32.f16.f16.f32 "
        "{%0,%1,%2,%3}, {%4,%5,%6,%7}, {%8,%9}, {%0,%1,%2,%3};"
        : "+f"(d[0]), "+f"(d[1]), "+f"(d[2]), "+f"(d[3])
        : "r"(a[0]), "r"(a[1]), "r"(a[2]), "r"(a[3]), "r"(b0), "r"(b1));
}
__device__ __forceinline__ uint32_t h2u(__half2 v) { return *(uint32_t*)&v; }

// 1-pass fp16 GEMM (A single, B single), warp tile 32x32
template<int KSTEPS, int STRIDE>
__device__ __forceinline__ void gemm_1p(uint32_t aS, uint32_t bS,
                                        int mrow, int ncol, int lane,
                                        float acc[2][4][4]) {
    const int arow = mrow + (lane & 15);
    const int asel = (lane >> 4) * 8;
    const int brow = ncol + ((lane >> 4) << 3) + (lane & 7);
    const int bsel = ((lane >> 3) & 1) * 8;
    #pragma unroll
    for (int ks = 0; ks < KSTEPS; ks++) {
        uint32_t ah[2][4], bs[2][4];
        #pragma unroll
        for (int mt = 0; mt < 2; mt++) {
            const uint32_t off = (uint32_t)(((arow + mt * 16) * STRIDE + ks * 16 + asel) * 2);
            ldsm4(ah[mt], aS + off);
        }
        #pragma unroll
        for (int j = 0; j < 2; j++) {
            const uint32_t off = (uint32_t)(((brow + j * 16) * STRIDE + ks * 16 + bsel) * 2);
            ldsm4(bs[j], bS + off);
        }
        #pragma unroll
        for (int mt = 0; mt < 2; mt++)
            #pragma unroll
            for (int nt = 0; nt < 4; nt++) {
                const int j = nt >> 1, hf = (nt & 1) * 2;
                mma_f16(acc[mt][nt], ah[mt], bs[j][hf], bs[j][hf + 1]);
            }
    }
}

// ---------------------------------------------------------------------------
// Kernel 1 (merged): stage nf tile once; P for all rows, R when base < N_DST
// ---------------------------------------------------------------------------
#define POFF_A   0        // 128 x 136 fp16 = 34816 B
#define POFF_WO  34816    // 64 x 136 fp16 = 17408 B
#define POFF_WN  52224    // 64 x 136 fp16 = 17408 B
#define PJ_SMEM  69632
#define PJ_BLOCKS 296

__global__ __launch_bounds__(256, 2)
void k_projT(const float* __restrict__ nf,
             const float* __restrict__ Wo,
             const float* __restrict__ Wn)
{
    extern __shared__ char smc[];
    const int tid = threadIdx.x, lane = tid & 31, wid = tid >> 5;
    const int mrow = (wid & 3) * 32, ncol = (wid >> 2) * 32;

    for (int i = tid; i < 64 * 128; i += 256) {
        const int n = i >> 7, k = i & 127;
        ((__half*)(smc + POFF_WO))[n * 136 + k] = __float2half(Wo[k * 64 + n]);
        ((__half*)(smc + POFF_WN))[n * 136 + k] = __float2half(Wn[k * 64 + n]);
    }
    const uint32_t aS = smem_u32(smc + POFF_A);
    const uint32_t bO = smem_u32(smc + POFF_WO);
    const uint32_t bN = smem_u32(smc + POFF_WN);

    const int ntile = (N_SRC + 127) >> 7;   // 782

    for (int tile = blockIdx.x; tile < ntile; tile += PJ_BLOCKS) {
        __syncthreads();
        const int base = tile * 128;
        #pragma unroll
        for (int t = 0; t < 8; t++) {
            const int idx = tid + 256 * t;
            const int r = idx >> 4, c16 = idx & 15;
            float4 v0 = make_float4(0.f, 0.f, 0.f, 0.f), v1 = v0;
            if (base + r < N_SRC) {
                const float4* row = (const float4*)(nf + (size_t)(base + r) * NODE_IN);
                v0 = row[c16 * 2];
                v1 = row[c16 * 2 + 1];
            }
            uint4 pk;
            pk.x = h2u(__floats2half2_rn(v0.x, v0.y));
            pk.y = h2u(__floats2half2_rn(v0.z, v0.w));
            pk.z = h2u(__floats2half2_rn(v1.x, v1.y));
            pk.w = h2u(__floats2half2_rn(v1.z, v1.w));
            *(uint4*)(smc + POFF_A + (size_t)r * 272 + c16 * 16) = pk;
        }
        __syncthreads();

        float acc[2][4][4];

        // ---- P = A @ Wo_top^T (fp16 out) ----
        #pragma unroll
        for (int a = 0; a < 2; a++)
            #pragma unroll
            for (int b = 0; b < 4; b++)
                #pragma unroll
                for (int c = 0; c < 4; c++) acc[a][b][c] = 0.f;
        gemm_1p<8, 136>(aS, bO, mrow, ncol, lane, acc);
        #pragma unroll
        for (int mt = 0; mt < 2; mt++) {
            const int r0 = base + mrow + mt * 16 + (lane >> 2);
            #pragma unroll
            for (int nt = 0; nt < 4; nt++) {
                const int c = ncol + nt * 8 + (lane & 3) * 2;
                if (r0 < N_SRC)
                    *(uint32_t*)(g_P + (size_t)r0 * HID + c) =
                        h2u(__floats2half2_rn(acc[mt][nt][0], acc[mt][nt][1]));
                if (r0 + 8 < N_SRC)
                    *(uint32_t*)(g_P + (size_t)(r0 + 8) * HID + c) =
                        h2u(__floats2half2_rn(acc[mt][nt][2], acc[mt][nt][3]));
            }
        }

        // ---- R = A @ Wn_top^T (fp32 out), only for rows < N_DST ----
        if (base < N_DST) {
            #pragma unroll
            for (int a = 0; a < 2; a++)
                #pragma unroll
                for (int b = 0; b < 4; b++)
                    #pragma unroll
                    for (int c = 0; c < 4; c++) acc[a][b][c] = 0.f;
            gemm_1p<8, 136>(aS, bN, mrow, ncol, lane, acc);
            #pragma unroll
            for (int mt = 0; mt < 2; mt++) {
                const int r0 = base + mrow + mt * 16 + (lane >> 2);
                #pragma unroll
                for (int nt = 0; nt < 4; nt++) {
                    const int c = ncol + nt * 8 + (lane & 3) * 2;
                    if (r0 < N_DST)
                        *(float2*)(g_R + (size_t)r0 * HID + c) =
                            make_float2(acc[mt][nt][0], acc[mt][nt][1]);
                    if (r0 + 8 < N_DST)
                        *(float2*)(g_R + (size_t)(r0 + 8) * HID + c) =
                            make_float2(acc[mt][nt][2], acc[mt][nt][3]);
                }
            }
        }
    }
}

// ---------------------------------------------------------------------------
// Kernel 2: R9 structure (32x32 warp tiles, 8-thread sparsemax, 3 syncs/tile)
//           with epilogue-1 writeback via stmatrix
// ---------------------------------------------------------------------------
#define OFF_E    0        // 128 x 72 fp16 = 18432
#define OFF_EO   18432    // e_out buffer   = 18432
#define OFF_W1   36864
#define OFF_W2   46080
#define OFF_W3   55296
#define OFF_HN   64512    // 16 x 72 fp16 (rows 8..15 stay zero)
#define OFF_LOG  66816    // 128 floats
#define OFF_TAU  67328
#define OFF_AMX  67360
#define OFF_V    67392
#define OFF_BE   67648
#define OFF_BO   67904
#define OFF_BN   68160
#define OFF_SRC  68416
#define OFF_C    68928
#define FS_SMEM  68944

__global__ __launch_bounds__(256, 2)
void k_fusedT(const float* __restrict__ ef,
              const int*   __restrict__ src_idx,
              const float* __restrict__ We,  const float* __restrict__ be,
              const float* __restrict__ Wa,  const float* __restrict__ ba,
              const float* __restrict__ wa,
              const float* __restrict__ Wo,  const float* __restrict__ bo,
              const float* __restrict__ Wn,  const float* __restrict__ bn,
              float* __restrict__ out)
{
    extern __shared__ char smc[];
    const int tid = threadIdx.x, lane = tid & 31, wid = tid >> 5;
    const int mrow = (wid & 3) * 32, ncol = (wid >> 2) * 32;

    float* sLog = (float*)(smc + OFF_LOG);
    float* sTau = (float*)(smc + OFF_TAU);
    float* sAmx = (float*)(smc + OFF_AMX);
    float* sV   = (float*)(smc + OFF_V);
    float* sBe  = (float*)(smc + OFF_BE);
    float* sBo  = (float*)(smc + OFF_BO);
    float* sBn  = (float*)(smc + OFF_BN);
    int*   sSrc = (int*)  (smc + OFF_SRC);

    for (int i = tid; i < 4096; i += 256) {
        const int n = i >> 6, k = i & 63;
        ((__half*)(smc + OFF_W1))[n * 72 + k] = __float2half(We[k * 64 + n]);
        ((__half*)(smc + OFF_W2))[n * 72 + k] = __float2half(Wo[(NODE_IN + k) * 64 + n]);
        ((__half*)(smc + OFF_W3))[n * 72 + k] = __float2half(Wn[(NODE_IN + k) * 64 + n]);
    }
    for (int i = tid; i < 288; i += 256)
        ((uint32_t*)(smc + OFF_HN + 1152))[i] = 0;
    if (tid < 64) {
        sBe[tid] = be[tid]; sBo[tid] = bo[tid]; sBn[tid] = bn[tid];
        float sv = 0.f;
        #pragma unroll 8
        for (int k = 0; k < 64; k++) sv = fmaf(Wa[tid * 64 + k], wa[k], sv);
        sV[tid] = sv;
    }
    if (tid == 64) {
        float sc = 0.f;
        for (int k = 0; k < 64; k++) sc = fmaf(ba[k], wa[k], sc);
        *(float*)(smc + OFF_C) = sc;
    }
    __syncthreads();
    const float cval = *(const float*)(smc + OFF_C);

    const uint32_t eS  = smem_u32(smc + OFF_E);
    const uint32_t eoS = smem_u32(smc + OFF_EO);
    const uint32_t w1 = smem_u32(smc + OFF_W1), w2 = smem_u32(smc + OFF_W2);
    const uint32_t w3 = smem_u32(smc + OFF_W3);
    const uint32_t hnS = smem_u32(smc + OFF_HN);

    // hoist GEMM3 B fragments (loop-invariant): warp owns cols wid*8..+7
    uint32_t b3[2][4];
    {
        const int nc = wid * 8;
        #pragma unroll
        for (int g = 0; g < 2; g++) {
            const uint32_t off = (uint32_t)(((nc + (lane & 7)) * 72 + (lane >> 3) * 8 + g * 32) * 2);
            ldsm4(b3[g], w3 + off);
        }
    }

    for (int tile = blockIdx.x; tile < NTILE; tile += gridDim.x) {
        // ---- stage E tile -> single fp16 (uint4 stores) + fused logits ----
        const float4* eg = (const float4*)(ef + (size_t)tile * 8192);
        #pragma unroll
        for (int t = 0; t < 4; t++) {
            const int idx = tid + 256 * t;       // 0..1023
            const int r = idx >> 3, c8 = idx & 7;
            const float4 v0 = eg[r * 16 + c8 * 2];
            const float4 v1 = eg[r * 16 + c8 * 2 + 1];
            uint4 pk;
            pk.x = h2u(__floats2half2_rn(v0.x, v0.y));
            pk.y = h2u(__floats2half2_rn(v0.z, v0.w));
            pk.z = h2u(__floats2half2_rn(v1.x, v1.y));
            pk.w = h2u(__floats2half2_rn(v1.z, v1.w));
            *(uint4*)(smc + OFF_E + (size_t)r * 144 + c8 * 16) = pk;
            const float* vv = sV + c8 * 8;
            float p = v0.x * vv[0] + v0.y * vv[1] + v0.z * vv[2] + v0.w * vv[3]
                    + v1.x * vv[4] + v1.y * vv[5] + v1.z * vv[6] + v1.w * vv[7];
            p += __shfl_xor_sync(0xffffffffu, p, 1);
            p += __shfl_xor_sync(0xffffffffu, p, 2);
            p += __shfl_xor_sync(0xffffffffu, p, 4);
            if ((tid & 7) == 0) sLog[r] = p;
        }
        if (tid < 128) sSrc[tid] = src_idx[tile * 128 + tid];
        __syncthreads();   // S1: E + logits visible

        // ---- sparsemax (8 threads of warp 0, overlaps GEMM1 elsewhere) ----
        if (tid < 8) {
            float z[16], amax = -3.4e38f;
            #pragma unroll
            for (int d = 0; d < 16; d++) {
                float raw = sLog[tid * 16 + d] + cval;
                raw = (raw > 0.f) ? raw : 0.01f * raw;
                sLog[tid * 16 + d] = raw;
                z[d] = raw; amax = fmaxf(amax, z[d]);
            }
            #pragma unroll
            for (int d = 0; d < 16; d++) z[d] -= amax;
            #pragma unroll
            for (int kk2 = 2; kk2 <= 16; kk2 <<= 1)
                #pragma unroll
                for (int j = kk2 >> 1; j > 0; j >>= 1)
                    #pragma unroll
                    for (int i = 0; i < 16; i++) {
                        const int l = i ^ j;
                        if (l > i) {
                            const bool up = ((i & kk2) == 0);
                            const float a0 = z[i], b0 = z[l];
                            if (up ? (a0 > b0) : (a0 < b0)) { z[i] = b0; z[l] = a0; }
                        }
                    }
            float cs = 0.f, cssel = 0.f, kk = 1.f;
            #pragma unroll
            for (int j = 1; j <= 16; j++) {
                const float zz = z[16 - j];
                cs += zz;
                if (1.f + (float)j * zz > cs) { kk = (float)j; cssel = cs; }
            }
            sTau[tid] = (cssel - 1.f) / kk;
            sAmx[tid] = amax;
        }

        float acc[2][4][4];

        // ---- GEMM1: e_out_pre = E @ We^T ----
        #pragma unroll
        for (int a = 0; a < 2; a++)
            #pragma unroll
            for (int b = 0; b < 4; b++)
                #pragma unroll
                for (int c = 0; c < 4; c++) acc[a][b][c] = 0.f;
        gemm_1p<4, 72>(eS, w1, mrow, ncol, lane, acc);

        // ---- epilogue1: relu(+be) -> e_out via stmatrix (2 instrs per mt) ----
        #pragma unroll
        for (int mt = 0; mt < 2; mt++) {
            #pragma unroll
            for (int p = 0; p < 2; p++) {
                const int c0 = ncol + p * 16 + (lane & 3) * 2;   // nt = 2p
                const int c1 = c0 + 8;                           // nt = 2p+1
                const uint32_t r0 = h2u(__floats2half2_rn(
                    fmaxf(acc[mt][2 * p][0] + sBe[c0],     0.f),
                    fmaxf(acc[mt][2 * p][1] + sBe[c0 + 1], 0.f)));
                const uint32_t r1 = h2u(__floats2half2_rn(
                    fmaxf(acc[mt][2 * p][2] + sBe[c0],     0.f),
                    fmaxf(acc[mt][2 * p][3] + sBe[c0 + 1], 0.f)));
                const uint32_t r2 = h2u(__floats2half2_rn(
                    fmaxf(acc[mt][2 * p + 1][0] + sBe[c1],     0.f),
                    fmaxf(acc[mt][2 * p + 1][1] + sBe[c1 + 1], 0.f)));
                const uint32_t r3 = h2u(__floats2half2_rn(
                    fmaxf(acc[mt][2 * p + 1][2] + sBe[c1],     0.f),
                    fmaxf(acc[mt][2 * p + 1][3] + sBe[c1 + 1], 0.f)));
                const int row = mrow + mt * 16 + (lane & 7) + ((lane >> 3) & 1) * 8;
                const int col = ncol + p * 16 + (lane >> 4) * 8;
                stsm4(eoS + (uint32_t)((row * 72 + col) * 2), r0, r1, r2, r3);
            }
        }
        __syncthreads();   // S2: e_out + tau visible

        // ---- GEMM2: m_pre = e_out @ Wo_bot^T ----
        #pragma unroll
        for (int a = 0; a < 2; a++)
            #pragma unroll
            for (int b = 0; b < 4; b++)
                #pragma unroll
                for (int c = 0; c < 4; c++) acc[a][b][c] = 0.f;
        gemm_1p<4, 72>(eoS, w2, mrow, ncol, lane, acc);

        // ---- epilogue2: m = relu(m_pre + P[src] + bo); alpha-weighted sum ----
        #pragma unroll
        for (int mt = 0; mt < 2; mt++) {
            const int ln = (mrow >> 4) + mt;
            const int r0 = mrow + mt * 16 + (lane >> 2);
            const int r1 = r0 + 8;
            const int s0 = sSrc[r0], s1 = sSrc[r1];
            const float at = sAmx[ln] + sTau[ln];
            const float al0 = fmaxf(sLog[r0] - at, 0.f);
            const float al1 = fmaxf(sLog[r1] - at, 0.f);
            #pragma unroll
            for (int nt = 0; nt < 4; nt++) {
                const int c = ncol + nt * 8 + (lane & 3) * 2;
                const uint32_t pv0 = *(const uint32_t*)(g_P + (size_t)s0 * HID + c);
                const uint32_t pv1 = *(const uint32_t*)(g_P + (size_t)s1 * HID + c);
                const float2 p0 = __half22float2(*(const __half2*)&pv0);
                const float2 p1 = __half22float2(*(const __half2*)&pv1);
                const float m00 = fmaxf(acc[mt][nt][0] + p0.x + sBo[c],     0.f);
                const float m01 = fmaxf(acc[mt][nt][1] + p0.y + sBo[c + 1], 0.f);
                const float m10 = fmaxf(acc[mt][nt][2] + p1.x + sBo[c],     0.f);
                const float m11 = fmaxf(acc[mt][nt][3] + p1.y + sBo[c + 1], 0.f);
                float sx = m00 * al0 + m10 * al1;
                float sy = m01 * al0 + m11 * al1;
                sx += __shfl_xor_sync(0xffffffffu, sx, 4);
                sy += __shfl_xor_sync(0xffffffffu, sy, 4);
                sx += __shfl_xor_sync(0xffffffffu, sx, 8);
                sy += __shfl_xor_sync(0xffffffffu, sy, 8);
                sx += __shfl_xor_sync(0xffffffffu, sx, 16);
                sy += __shfl_xor_sync(0xffffffffu, sy, 16);
                if (lane < 4)
                    *(uint32_t*)(smc + OFF_HN + (size_t)(ln * 72 + c) * 2) =
                        h2u(__floats2half2_rn(sx, sy));
            }
        }
        __syncthreads();   // S3: HN visible

        // ---- GEMM3 (M=16 padded, 1-pass): out = relu(R + HN @ Wn_bot^T + bn) ----
        {
            float acc3[4] = {0.f, 0.f, 0.f, 0.f};
            #pragma unroll
            for (int ks = 0; ks < 4; ks++) {
                uint32_t a3[4];
                const uint32_t aoff = (uint32_t)(((lane & 15) * 72 + ks * 16 + (lane >> 4) * 8) * 2);
                ldsm4(a3, hnS + aoff);
                const int g = ks >> 1, pr = (ks & 1) * 2;
                mma_f16(acc3, a3, b3[g][pr], b3[g][pr + 1]);
            }
            const int node = tile * 8 + (lane >> 2);
            const int col = wid * 8 + (lane & 3) * 2;
            const float2 r2 = *(const float2*)(g_R + (size_t)node * HID + col);
            const float o0 = acc3[0] + r2.x + sBn[col];
            const float o1 = acc3[1] + r2.y + sBn[col + 1];
            *(float2*)(out + (size_t)node * HID + col) =
                make_float2(fmaxf(o0, 0.f), fmaxf(o1, 0.f));
        }
        // no trailing sync: next staging targets (E/sLog/sSrc) have no readers
        // past S3; GEMM3 reads only HN/g_R/sBn.
    }
}

// ---------------------------------------------------------------------------
extern "C" void kernel_launch(void* const* d_in, const int* in_sizes, int n_in,
                              void* d_out, int out_size)
{
    const float* nf = (const float*)d_in[0];
    const float* ef = (const float*)d_in[1];
    const int*   si = (const int*)  d_in[2];
    const float* We = (const float*)d_in[3];
    const float* be = (const float*)d_in[4];
    const float* Wa = (const float*)d_in[5];
    const float* ba = (const float*)d_in[6];
    const float* wa = (const float*)d_in[7];
    const float* Wo = (const float*)d_in[8];
    const float* bo = (const float*)d_in[9];
    const float* Wn = (const float*)d_in[10];
    const float* bn = (const float*)d_in[11];
    float* out = (float*)d_out;

    cudaFuncSetAttribute(k_projT,  cudaFuncAttributeMaxDynamicSharedMemorySize, PJ_SMEM);
    cudaFuncSetAttribute(k_fusedT, cudaFuncAttributeMaxDynamicSharedMemorySize, FS_SMEM);

    k_projT<<<PJ_BLOCKS, 256, PJ_SMEM>>>(nf, Wo, Wn);
    k_fusedT<<<296, 256, FS_SMEM>>>(ef, si, We, be, Wa, ba, wa, Wo, bo, Wn, bn, out);
}

// round 12
// speedup vs baseline: 1.1613x; 1.1328x over previous
#include <cuda_runtime.h>
#include <cuda_fp16.h>
#include <cstdint>
#include <cstddef>

#define N_SRC   100000
#define N_DST   50000
#define NODE_IN 128
#define HID     64
#define NTILE   (N_DST / 8)

__device__ __half g_P[(size_t)N_SRC * HID];   // fp16 storage (12.8 MB, L2-resident)
__device__ float  g_R[(size_t)N_DST * HID];

// ---------------------------------------------------------------------------
__device__ __forceinline__ uint32_t smem_u32(const void* p) {
    uint32_t a;
    asm("{ .reg .u64 t; cvta.to.shared.u64 t, %1; cvt.u32.u64 %0, t; }" : "=r"(a) : "l"(p));
    return a;
}
__device__ __forceinline__ void ldsm4(uint32_t r[4], uint32_t addr) {
    asm volatile("ldmatrix.sync.aligned.m8n8.x4.shared.b16 {%0,%1,%2,%3}, [%4];"
        : "=r"(r[0]), "=r"(r[1]), "=r"(r[2]), "=r"(r[3]) : "r"(addr));
}
__device__ __forceinline__ void mma_f16(float d[4], const uint32_t a[4],
                                        uint32_t b0, uint32_t b1) {
    asm volatile("mma.sync.aligned.m16n8k16.row.col.f32.f16.f16.f32 "
        "{%0,%1,%2,%3}, {%4,%5,%6,%7}, {%8,%9}, {%0,%1,%2,%3};"
        : "+f"(d[0]), "+f"(d[1]), "+f"(d[2]), "+f"(d[3])
        : "r"(a[0]), "r"(a[1]), "r"(a[2]), "r"(a[3]), "r"(b0), "r"(b1));
}
__device__ __forceinline__ uint32_t h2u(__half2 v) { return *(uint32_t*)&v; }

// 1-pass fp16 GEMM (A single, B single), warp tile 32x32
template<int KSTEPS, int STRIDE>
__device__ __forceinline__ void gemm_1p(uint32_t aS, uint32_t bS,
                                        int mrow, int ncol, int lane,
                                        float acc[2][4][4]) {
    const int arow = mrow + (lane & 15);
    const int asel = (lane >> 4) * 8;
    const int brow = ncol + ((lane >> 4) << 3) + (lane & 7);
    const int bsel = ((lane >> 3) & 1) * 8;
    #pragma unroll
    for (int ks = 0; ks < KSTEPS; ks++) {
        uint32_t ah[2][4], bs[2][4];
        #pragma unroll
        for (int mt = 0; mt < 2; mt++) {
            const uint32_t off = (uint32_t)(((arow + mt * 16) * STRIDE + ks * 16 + asel) * 2);
            ldsm4(ah[mt], aS + off);
        }
        #pragma unroll
        for (int j = 0; j < 2; j++) {
            const uint32_t off = (uint32_t)(((brow + j * 16) * STRIDE + ks * 16 + bsel) * 2);
            ldsm4(bs[j], bS + off);
        }
        #pragma unroll
        for (int mt = 0; mt < 2; mt++)
            #pragma unroll
            for (int nt = 0; nt < 4; nt++) {
                const int j = nt >> 1, hf = (nt & 1) * 2;
                mma_f16(acc[mt][nt], ah[mt], bs[j][hf], bs[j][hf + 1]);
            }
    }
}

// ---------------------------------------------------------------------------
// Kernel 1: P(fp16) = nf @ Wo_top, R(fp32) = nf[:N_DST] @ Wn_top  (R9 version)
// ---------------------------------------------------------------------------
#define POFF_A  0        // 128 x 136 fp16 = 34816 B
#define POFF_W  34816    // 64 x 136 fp16 = 17408 B
#define PJ_SMEM 52224
#define PJ_BLOCKS 296
#define PJ_PSPLIT 197

__global__ __launch_bounds__(256, 2)
void k_projT(const float* __restrict__ nf,
             const float* __restrict__ Wo,
             const float* __restrict__ Wn)
{
    extern __shared__ char smc[];
    const int tid = threadIdx.x, lane = tid & 31, wid = tid >> 5;
    const int mrow = (wid & 3) * 32, ncol = (wid >> 2) * 32;

    const bool isP = (blockIdx.x < PJ_PSPLIT);
    const float* W = isP ? Wo : Wn;
    const int limit = isP ? N_SRC : N_DST;
    const int ntile = (limit + 127) >> 7;
    const int t0 = isP ? blockIdx.x : (blockIdx.x - PJ_PSPLIT);
    const int ts = isP ? PJ_PSPLIT : (PJ_BLOCKS - PJ_PSPLIT);

    for (int i = tid; i < 64 * 128; i += 256) {
        const int n = i >> 7, k = i & 127;
        ((__half*)(smc + POFF_W))[n * 136 + k] = __float2half(W[k * 64 + n]);
    }
    const uint32_t aS = smem_u32(smc + POFF_A);
    const uint32_t bS = smem_u32(smc + POFF_W);

    for (int tile = t0; tile < ntile; tile += ts) {
        __syncthreads();
        const int base = tile * 128;
        #pragma unroll
        for (int t = 0; t < 8; t++) {
            const int idx = tid + 256 * t;
            const int r = idx >> 4, c16 = idx & 15;
            float4 v0 = make_float4(0.f, 0.f, 0.f, 0.f), v1 = v0;
            if (base + r < limit) {
                const float4* row = (const float4*)(nf + (size_t)(base + r) * NODE_IN);
                v0 = row[c16 * 2];
                v1 = row[c16 * 2 + 1];
            }
            uint4 pk;
            pk.x = h2u(__floats2half2_rn(v0.x, v0.y));
            pk.y = h2u(__floats2half2_rn(v0.z, v0.w));
            pk.z = h2u(__floats2half2_rn(v1.x, v1.y));
            pk.w = h2u(__floats2half2_rn(v1.z, v1.w));
            *(uint4*)(smc + POFF_A + (size_t)r * 272 + c16 * 16) = pk;
        }
        __syncthreads();

        float acc[2][4][4];
        #pragma unroll
        for (int a = 0; a < 2; a++)
            #pragma unroll
            for (int b = 0; b < 4; b++)
                #pragma unroll
                for (int c = 0; c < 4; c++) acc[a][b][c] = 0.f;

        gemm_1p<8, 136>(aS, bS, mrow, ncol, lane, acc);

        #pragma unroll
        for (int mt = 0; mt < 2; mt++) {
            const int r0 = base + mrow + mt * 16 + (lane >> 2);
            #pragma unroll
            for (int nt = 0; nt < 4; nt++) {
                const int c = ncol + nt * 8 + (lane & 3) * 2;
                if (isP) {
                    if (r0 < limit)
                        *(uint32_t*)(g_P + (size_t)r0 * HID + c) =
                            h2u(__floats2half2_rn(acc[mt][nt][0], acc[mt][nt][1]));
                    if (r0 + 8 < limit)
                        *(uint32_t*)(g_P + (size_t)(r0 + 8) * HID + c) =
                            h2u(__floats2half2_rn(acc[mt][nt][2], acc[mt][nt][3]));
                } else {
                    if (r0 < limit)
                        *(float2*)(g_R + (size_t)r0 * HID + c) =
                            make_float2(acc[mt][nt][0], acc[mt][nt][1]);
                    if (r0 + 8 < limit)
                        *(float2*)(g_R + (size_t)(r0 + 8) * HID + c) =
                            make_float2(acc[mt][nt][2], acc[mt][nt][3]);
                }
            }
        }
    }
}

// ---------------------------------------------------------------------------
// Kernel 2: R9 structure + software prefetch (edge tile + P rows)
// ---------------------------------------------------------------------------
#define OFF_E    0        // 128 x 72 fp16 = 18432
#define OFF_EO   18432    // e_out buffer   = 18432
#define OFF_W1   36864
#define OFF_W2   46080
#define OFF_W3   55296
#define OFF_HN   64512    // 16 x 72 fp16 (rows 8..15 stay zero)
#define OFF_LOG  66816    // 128 floats
#define OFF_TAU  67328
#define OFF_AMX  67360
#define OFF_V    67392
#define OFF_BE   67648
#define OFF_BO   67904
#define OFF_BN   68160
#define OFF_SRC  68416
#define OFF_C    68928
#define FS_SMEM  68944

__global__ __launch_bounds__(256, 2)
void k_fusedT(const float* __restrict__ ef,
              const int*   __restrict__ src_idx,
              const float* __restrict__ We,  const float* __restrict__ be,
              const float* __restrict__ Wa,  const float* __restrict__ ba,
              const float* __restrict__ wa,
              const float* __restrict__ Wo,  const float* __restrict__ bo,
              const float* __restrict__ Wn,  const float* __restrict__ bn,
              float* __restrict__ out)
{
    extern __shared__ char smc[];
    const int tid = threadIdx.x, lane = tid & 31, wid = tid >> 5;
    const int mrow = (wid & 3) * 32, ncol = (wid >> 2) * 32;

    float* sLog = (float*)(smc + OFF_LOG);
    float* sTau = (float*)(smc + OFF_TAU);
    float* sAmx = (float*)(smc + OFF_AMX);
    float* sV   = (float*)(smc + OFF_V);
    float* sBe  = (float*)(smc + OFF_BE);
    float* sBo  = (float*)(smc + OFF_BO);
    float* sBn  = (float*)(smc + OFF_BN);
    int*   sSrc = (int*)  (smc + OFF_SRC);

    for (int i = tid; i < 4096; i += 256) {
        const int n = i >> 6, k = i & 63;
        ((__half*)(smc + OFF_W1))[n * 72 + k] = __float2half(We[k * 64 + n]);
        ((__half*)(smc + OFF_W2))[n * 72 + k] = __float2half(Wo[(NODE_IN + k) * 64 + n]);
        ((__half*)(smc + OFF_W3))[n * 72 + k] = __float2half(Wn[(NODE_IN + k) * 64 + n]);
    }
    for (int i = tid; i < 288; i += 256)
        ((uint32_t*)(smc + OFF_HN + 1152))[i] = 0;
    if (tid < 64) {
        sBe[tid] = be[tid]; sBo[tid] = bo[tid]; sBn[tid] = bn[tid];
        float sv = 0.f;
        #pragma unroll 8
        for (int k = 0; k < 64; k++) sv = fmaf(Wa[tid * 64 + k], wa[k], sv);
        sV[tid] = sv;
    }
    if (tid == 64) {
        float sc = 0.f;
        for (int k = 0; k < 64; k++) sc = fmaf(ba[k], wa[k], sc);
        *(float*)(smc + OFF_C) = sc;
    }
    __syncthreads();
    const float cval = *(const float*)(smc + OFF_C);

    const uint32_t eS  = smem_u32(smc + OFF_E);
    const uint32_t eoS = smem_u32(smc + OFF_EO);
    const uint32_t w1 = smem_u32(smc + OFF_W1), w2 = smem_u32(smc + OFF_W2);
    const uint32_t w3 = smem_u32(smc + OFF_W3);
    const uint32_t hnS = smem_u32(smc + OFF_HN);

    // hoist GEMM3 B fragments (loop-invariant)
    uint32_t b3[2][4];
    {
        const int nc = wid * 8;
        #pragma unroll
        for (int g = 0; g < 2; g++) {
            const uint32_t off = (uint32_t)(((nc + (lane & 7)) * 72 + (lane >> 3) * 8 + g * 32) * 2);
            ldsm4(b3[g], w3 + off);
        }
    }

    // -------- edge-tile prefetch (registers) --------
    int tile = blockIdx.x;
    float4 ev[8];
    int srcv = 0;
    if (tile < NTILE) {
        const float4* eg = (const float4*)(ef + (size_t)tile * 8192);
        #pragma unroll
        for (int t = 0; t < 4; t++) {
            const int idx = tid + 256 * t;
            const int r = idx >> 3, c8 = idx & 7;
            ev[2 * t]     = eg[r * 16 + c8 * 2];
            ev[2 * t + 1] = eg[r * 16 + c8 * 2 + 1];
        }
        if (tid < 128) srcv = src_idx[tile * 128 + tid];
    }

    for (; tile < NTILE; tile += gridDim.x) {
        // ---- staging from REGISTERS -> fp16 smem + fused logits ----
        #pragma unroll
        for (int t = 0; t < 4; t++) {
            const int idx = tid + 256 * t;
            const int r = idx >> 3, c8 = idx & 7;
            const float4 v0 = ev[2 * t];
            const float4 v1 = ev[2 * t + 1];
            uint4 pk;
            pk.x = h2u(__floats2half2_rn(v0.x, v0.y));
            pk.y = h2u(__floats2half2_rn(v0.z, v0.w));
            pk.z = h2u(__floats2half2_rn(v1.x, v1.y));
            pk.w = h2u(__floats2half2_rn(v1.z, v1.w));
            *(uint4*)(smc + OFF_E + (size_t)r * 144 + c8 * 16) = pk;
            const float* vv = sV + c8 * 8;
            float p = v0.x * vv[0] + v0.y * vv[1] + v0.z * vv[2] + v0.w * vv[3]
                    + v1.x * vv[4] + v1.y * vv[5] + v1.z * vv[6] + v1.w * vv[7];
            p += __shfl_xor_sync(0xffffffffu, p, 1);
            p += __shfl_xor_sync(0xffffffffu, p, 2);
            p += __shfl_xor_sync(0xffffffffu, p, 4);
            if ((tid & 7) == 0) sLog[r] = p;
        }
        if (tid < 128) sSrc[tid] = srcv;
        __syncthreads();   // S1: E + logits + src visible

        // ---- sparsemax (8 threads of warp 0) ----
        if (tid < 8) {
            float z[16], amax = -3.4e38f;
            #pragma unroll
            for (int d = 0; d < 16; d++) {
                float raw = sLog[tid * 16 + d] + cval;
                raw = (raw > 0.f) ? raw : 0.01f * raw;
                sLog[tid * 16 + d] = raw;
                z[d] = raw; amax = fmaxf(amax, z[d]);
            }
            #pragma unroll
            for (int d = 0; d < 16; d++) z[d] -= amax;
            #pragma unroll
            for (int kk2 = 2; kk2 <= 16; kk2 <<= 1)
                #pragma unroll
                for (int j = kk2 >> 1; j > 0; j >>= 1)
                    #pragma unroll
                    for (int i = 0; i < 16; i++) {
                        const int l = i ^ j;
                        if (l > i) {
                            const bool up = ((i & kk2) == 0);
                            const float a0 = z[i], b0 = z[l];
                            if (up ? (a0 > b0) : (a0 < b0)) { z[i] = b0; z[l] = a0; }
                        }
                    }
            float cs = 0.f, cssel = 0.f, kk = 1.f;
            #pragma unroll
            for (int j = 1; j <= 16; j++) {
                const float zz = z[16 - j];
                cs += zz;
                if (1.f + (float)j * zz > cs) { kk = (float)j; cssel = cs; }
            }
            sTau[tid] = (cssel - 1.f) / kk;
            sAmx[tid] = amax;
        }

        // ---- P-row prefetch (overlaps GEMM1+epi1+GEMM2) ----
        uint32_t pv0[2][4], pv1[2][4];
        #pragma unroll
        for (int mt = 0; mt < 2; mt++) {
            const int r0 = mrow + mt * 16 + (lane >> 2);
            const int s0 = sSrc[r0], s1 = sSrc[r0 + 8];
            #pragma unroll
            for (int nt = 0; nt < 4; nt++) {
                const int c = ncol + nt * 8 + (lane & 3) * 2;
                pv0[mt][nt] = *(const uint32_t*)(g_P + (size_t)s0 * HID + c);
                pv1[mt][nt] = *(const uint32_t*)(g_P + (size_t)s1 * HID + c);
            }
        }

        float acc[2][4][4];

        // ---- GEMM1: e_out_pre = E @ We^T ----
        #pragma unroll
        for (int a = 0; a < 2; a++)
            #pragma unroll
            for (int b = 0; b < 4; b++)
                #pragma unroll
                for (int c = 0; c < 4; c++) acc[a][b][c] = 0.f;
        gemm_1p<4, 72>(eS, w1, mrow, ncol, lane, acc);

        // ---- epilogue1: relu(+be) -> e_out buffer ----
        #pragma unroll
        for (int mt = 0; mt < 2; mt++) {
            const int r0 = mrow + mt * 16 + (lane >> 2);
            #pragma unroll
            for (int nt = 0; nt < 4; nt++) {
                const int c = ncol + nt * 8 + (lane & 3) * 2;
                const float x0 = fmaxf(acc[mt][nt][0] + sBe[c],     0.f);
                const float x1 = fmaxf(acc[mt][nt][1] + sBe[c + 1], 0.f);
                const float x2 = fmaxf(acc[mt][nt][2] + sBe[c],     0.f);
                const float x3 = fmaxf(acc[mt][nt][3] + sBe[c + 1], 0.f);
                *(uint32_t*)(smc + OFF_EO + (size_t)(r0 * 72 + c) * 2) =
                    h2u(__floats2half2_rn(x0, x1));
                *(uint32_t*)(smc + OFF_EO + (size_t)((r0 + 8) * 72 + c) * 2) =
                    h2u(__floats2half2_rn(x2, x3));
            }
        }
        __syncthreads();   // S2: e_out + tau visible

        // ---- GEMM2: m_pre = e_out @ Wo_bot^T ----
        #pragma unroll
        for (int a = 0; a < 2; a++)
            #pragma unroll
            for (int b = 0; b < 4; b++)
                #pragma unroll
                for (int c = 0; c < 4; c++) acc[a][b][c] = 0.f;
        gemm_1p<4, 72>(eoS, w2, mrow, ncol, lane, acc);

        // ---- epilogue2: m = relu(acc + P + bo); alpha-weighted sum -> HN ----
        #pragma unroll
        for (int mt = 0; mt < 2; mt++) {
            const int ln = (mrow >> 4) + mt;
            const int r0 = mrow + mt * 16 + (lane >> 2);
            const int r1 = r0 + 8;
            const float at = sAmx[ln] + sTau[ln];
            const float al0 = fmaxf(sLog[r0] - at, 0.f);
            const float al1 = fmaxf(sLog[r1] - at, 0.f);
            #pragma unroll
            for (int nt = 0; nt < 4; nt++) {
                const int c = ncol + nt * 8 + (lane & 3) * 2;
                const float2 p0 = __half22float2(*(const __half2*)&pv0[mt][nt]);
                const float2 p1 = __half22float2(*(const __half2*)&pv1[mt][nt]);
                const float m00 = fmaxf(acc[mt][nt][0] + p0.x + sBo[c],     0.f);
                const float m01 = fmaxf(acc[mt][nt][1] + p0.y + sBo[c + 1], 0.f);
                const float m10 = fmaxf(acc[mt][nt][2] + p1.x + sBo[c],     0.f);
                const float m11 = fmaxf(acc[mt][nt][3] + p1.y + sBo[c + 1], 0.f);
                float sx = m00 * al0 + m10 * al1;
                float sy = m01 * al0 + m11 * al1;
                sx += __shfl_xor_sync(0xffffffffu, sx, 4);
                sy += __shfl_xor_sync(0xffffffffu, sy, 4);
                sx += __shfl_xor_sync(0xffffffffu, sx, 8);
                sy += __shfl_xor_sync(0xffffffffu, sy, 8);
                sx += __shfl_xor_sync(0xffffffffu, sx, 16);
                sy += __shfl_xor_sync(0xffffffffu, sy, 16);
                if (lane < 4)
                    *(uint32_t*)(smc + OFF_HN + (size_t)(ln * 72 + c) * 2) =
                        h2u(__floats2half2_rn(sx, sy));
            }
        }
        __syncthreads();   // S3: HN visible

        // ---- prefetch NEXT tile (overlaps GEMM3 + out stores) ----
        {
            const int tnext = tile + gridDim.x;
            if (tnext < NTILE) {
                const float4* eg = (const float4*)(ef + (size_t)tnext * 8192);
                #pragma unroll
                for (int t = 0; t < 4; t++) {
                    const int idx = tid + 256 * t;
                    const int r = idx >> 3, c8 = idx & 7;
                    ev[2 * t]     = eg[r * 16 + c8 * 2];
                    ev[2 * t + 1] = eg[r * 16 + c8 * 2 + 1];
                }
                if (tid < 128) srcv = src_idx[tnext * 128 + tid];
            }
        }

        // ---- GEMM3 (M=16 padded, 1-pass): out = relu(R + HN @ Wn_bot^T + bn) ----
        {
            float acc3[4] = {0.f, 0.f, 0.f, 0.f};
            #pragma unroll
            for (int ks = 0; ks < 4; ks++) {
                uint32_t a3[4];
                const uint32_t aoff = (uint32_t)(((lane & 15) * 72 + ks * 16 + (lane >> 4) * 8) * 2);
                ldsm4(a3, hnS + aoff);
                const int g = ks >> 1, pr = (ks & 1) * 2;
                mma_f16(acc3, a3, b3[g][pr], b3[g][pr + 1]);
            }
            const int node = tile * 8 + (lane >> 2);
            const int col = wid * 8 + (lane & 3) * 2;
            const float2 r2 = *(const float2*)(g_R + (size_t)node * HID + col);
            const float o0 = acc3[0] + r2.x + sBn[col];
            const float o1 = acc3[1] + r2.y + sBn[col + 1];
            *(float2*)(out + (size_t)node * HID + col) =
                make_float2(fmaxf(o0, 0.f), fmaxf(o1, 0.f));
        }
        // no trailing sync (same hazard argument as R9)
    }
}

// ---------------------------------------------------------------------------
extern "C" void kernel_launch(void* const* d_in, const int* in_sizes, int n_in,
                              void* d_out, int out_size)
{
    const float* nf = (const float*)d_in[0];
    const float* ef = (const float*)d_in[1];
    const int*   si = (const int*)  d_in[2];
    const float* We = (const float*)d_in[3];
    const float* be = (const float*)d_in[4];
    const float* Wa = (const float*)d_in[5];
    const float* ba = (const float*)d_in[6];
    const float* wa = (const float*)d_in[7];
    const float* Wo = (const float*)d_in[8];
    const float* bo = (const float*)d_in[9];
    const float* Wn = (const float*)d_in[10];
    const float* bn = (const float*)d_in[11];
    float* out = (float*)d_out;

    cudaFuncSetAttribute(k_projT,  cudaFuncAttributeMaxDynamicSharedMemorySize, PJ_SMEM);
    cudaFuncSetAttribute(k_fusedT, cudaFuncAttributeMaxDynamicSharedMemorySize, FS_SMEM);

    k_projT<<<PJ_BLOCKS, 256, PJ_SMEM>>>(nf, Wo, Wn);
    k_fusedT<<<296, 256, FS_SMEM>>>(ef, si, We, be, Wa, ba, wa, Wo, bo, Wn, bn, out);
}

// round 13
// speedup vs baseline: 1.2737x; 1.0968x over previous
#include <cuda_runtime.h>
#include <cuda_fp16.h>
#include <cstdint>
#include <cstddef>

#define N_SRC   100000
#define N_DST   50000
#define NODE_IN 128
#define HID     64
#define NTILE   (N_DST / 8)

// g_P stored PERMUTED per 32-col half: perm_off = half*32 + 8*(lane&3) + 2*nt + b
// (writer and reader both use MMA D-fragment order, so the gather is contiguous)
__device__ __half g_P[(size_t)N_SRC * HID];
__device__ float  g_R[(size_t)N_DST * HID];

// ---------------------------------------------------------------------------
__device__ __forceinline__ uint32_t smem_u32(const void* p) {
    uint32_t a;
    asm("{ .reg .u64 t; cvta.to.shared.u64 t, %1; cvt.u32.u64 %0, t; }" : "=r"(a) : "l"(p));
    return a;
}
__device__ __forceinline__ void ldsm4(uint32_t r[4], uint32_t addr) {
    asm volatile("ldmatrix.sync.aligned.m8n8.x4.shared.b16 {%0,%1,%2,%3}, [%4];"
        : "=r"(r[0]), "=r"(r[1]), "=r"(r[2]), "=r"(r[3]) : "r"(addr));
}
__device__ __forceinline__ void mma_f16(float d[4], const uint32_t a[4],
                                        uint32_t b0, uint32_t b1) {
    asm volatile("mma.sync.aligned.m16n8k16.row.col.f32.f16.f16.f32 "
        "{%0,%1,%2,%3}, {%4,%5,%6,%7}, {%8,%9}, {%0,%1,%2,%3};"
        : "+f"(d[0]), "+f"(d[1]), "+f"(d[2]), "+f"(d[3])
        : "r"(a[0]), "r"(a[1]), "r"(a[2]), "r"(a[3]), "r"(b0), "r"(b1));
}
__device__ __forceinline__ uint32_t h2u(__half2 v) { return *(uint32_t*)&v; }

// 1-pass fp16 GEMM (A single, B single), warp tile 32x32
template<int KSTEPS, int STRIDE>
__device__ __forceinline__ void gemm_1p(uint32_t aS, uint32_t bS,
                                        int mrow, int ncol, int lane,
                                        float acc[2][4][4]) {
    const int arow = mrow + (lane & 15);
    const int asel = (lane >> 4) * 8;
    const int brow = ncol + ((lane >> 4) << 3) + (lane & 7);
    const int bsel = ((lane >> 3) & 1) * 8;
    #pragma unroll
    for (int ks = 0; ks < KSTEPS; ks++) {
        uint32_t ah[2][4], bs[2][4];
        #pragma unroll
        for (int mt = 0; mt < 2; mt++) {
            const uint32_t off = (uint32_t)(((arow + mt * 16) * STRIDE + ks * 16 + asel) * 2);
            ldsm4(ah[mt], aS + off);
        }
        #pragma unroll
        for (int j = 0; j < 2; j++) {
            const uint32_t off = (uint32_t)(((brow + j * 16) * STRIDE + ks * 16 + bsel) * 2);
            ldsm4(bs[j], bS + off);
        }
        #pragma unroll
        for (int mt = 0; mt < 2; mt++)
            #pragma unroll
            for (int nt = 0; nt < 4; nt++) {
                const int j = nt >> 1, hf = (nt & 1) * 2;
                mma_f16(acc[mt][nt], ah[mt], bs[j][hf], bs[j][hf + 1]);
            }
    }
}

// ---------------------------------------------------------------------------
// Kernel 1: P(fp16, permuted) = nf @ Wo_top, R(fp32) = nf[:N_DST] @ Wn_top
//           with register prefetch of staging loads
// ---------------------------------------------------------------------------
#define POFF_A  0        // 128 x 136 fp16 = 34816 B
#define POFF_W  34816    // 64 x 136 fp16 = 17408 B
#define PJ_SMEM 52224
#define PJ_BLOCKS 296
#define PJ_PSPLIT 197

__global__ __launch_bounds__(256, 2)
void k_projT(const float* __restrict__ nf,
             const float* __restrict__ Wo,
             const float* __restrict__ Wn)
{
    extern __shared__ char smc[];
    const int tid = threadIdx.x, lane = tid & 31, wid = tid >> 5;
    const int mrow = (wid & 3) * 32, ncol = (wid >> 2) * 32;

    const bool isP = (blockIdx.x < PJ_PSPLIT);
    const float* W = isP ? Wo : Wn;
    const int limit = isP ? N_SRC : N_DST;
    const int ntile = (limit + 127) >> 7;
    const int t0 = isP ? blockIdx.x : (blockIdx.x - PJ_PSPLIT);
    const int ts = isP ? PJ_PSPLIT : (PJ_BLOCKS - PJ_PSPLIT);

    for (int i = tid; i < 64 * 128; i += 256) {
        const int n = i >> 7, k = i & 127;
        ((__half*)(smc + POFF_W))[n * 136 + k] = __float2half(W[k * 64 + n]);
    }
    const uint32_t aS = smem_u32(smc + POFF_A);
    const uint32_t bS = smem_u32(smc + POFF_W);

    // prefetch first tile into registers
    int tile = t0;
    float4 ev[16];
    if (tile < ntile) {
        const int base = tile * 128;
        #pragma unroll
        for (int t = 0; t < 8; t++) {
            const int idx = tid + 256 * t;
            const int r = idx >> 4, c16 = idx & 15;
            ev[2 * t] = make_float4(0.f, 0.f, 0.f, 0.f);
            ev[2 * t + 1] = ev[2 * t];
            if (base + r < limit) {
                const float4* row = (const float4*)(nf + (size_t)(base + r) * NODE_IN);
                ev[2 * t]     = row[c16 * 2];
                ev[2 * t + 1] = row[c16 * 2 + 1];
            }
        }
    }

    for (; tile < ntile; tile += ts) {
        __syncthreads();
        const int base = tile * 128;
        #pragma unroll
        for (int t = 0; t < 8; t++) {
            const int idx = tid + 256 * t;
            const int r = idx >> 4, c16 = idx & 15;
            const float4 v0 = ev[2 * t], v1 = ev[2 * t + 1];
            uint4 pk;
            pk.x = h2u(__floats2half2_rn(v0.x, v0.y));
            pk.y = h2u(__floats2half2_rn(v0.z, v0.w));
            pk.z = h2u(__floats2half2_rn(v1.x, v1.y));
            pk.w = h2u(__floats2half2_rn(v1.z, v1.w));
            *(uint4*)(smc + POFF_A + (size_t)r * 272 + c16 * 16) = pk;
        }
        __syncthreads();

        float acc[2][4][4];
        #pragma unroll
        for (int a = 0; a < 2; a++)
            #pragma unroll
            for (int b = 0; b < 4; b++)
                #pragma unroll
                for (int c = 0; c < 4; c++) acc[a][b][c] = 0.f;

        gemm_1p<8, 136>(aS, bS, mrow, ncol, lane, acc);

        // prefetch next tile (overlaps writeback)
        {
            const int tn = tile + ts;
            if (tn < ntile) {
                const int nbase = tn * 128;
                #pragma unroll
                for (int t = 0; t < 8; t++) {
                    const int idx = tid + 256 * t;
                    const int r = idx >> 4, c16 = idx & 15;
                    ev[2 * t] = make_float4(0.f, 0.f, 0.f, 0.f);
                    ev[2 * t + 1] = ev[2 * t];
                    if (nbase + r < limit) {
                        const float4* row = (const float4*)(nf + (size_t)(nbase + r) * NODE_IN);
                        ev[2 * t]     = row[c16 * 2];
                        ev[2 * t + 1] = row[c16 * 2 + 1];
                    }
                }
            }
        }

        #pragma unroll
        for (int mt = 0; mt < 2; mt++) {
            const int r0 = base + mrow + mt * 16 + (lane >> 2);
            if (isP) {
                // permuted uint4 store: offsets ncol + 8*(lane&3) + 2*nt
                const int po = ncol + 8 * (lane & 3);
                uint4 q0, q1;
                q0.x = h2u(__floats2half2_rn(acc[mt][0][0], acc[mt][0][1]));
                q0.y = h2u(__floats2half2_rn(acc[mt][1][0], acc[mt][1][1]));
                q0.z = h2u(__floats2half2_rn(acc[mt][2][0], acc[mt][2][1]));
                q0.w = h2u(__floats2half2_rn(acc[mt][3][0], acc[mt][3][1]));
                q1.x = h2u(__floats2half2_rn(acc[mt][0][2], acc[mt][0][3]));
                q1.y = h2u(__floats2half2_rn(acc[mt][1][2], acc[mt][1][3]));
                q1.z = h2u(__floats2half2_rn(acc[mt][2][2], acc[mt][2][3]));
                q1.w = h2u(__floats2half2_rn(acc[mt][3][2], acc[mt][3][3]));
                if (r0 < limit)
                    *(uint4*)(g_P + (size_t)r0 * HID + po) = q0;
                if (r0 + 8 < limit)
                    *(uint4*)(g_P + (size_t)(r0 + 8) * HID + po) = q1;
            } else {
                #pragma unroll
                for (int nt = 0; nt < 4; nt++) {
                    const int c = ncol + nt * 8 + (lane & 3) * 2;
                    if (r0 < limit)
                        *(float2*)(g_R + (size_t)r0 * HID + c) =
                            make_float2(acc[mt][nt][0], acc[mt][nt][1]);
                    if (r0 + 8 < limit)
                        *(float2*)(g_R + (size_t)(r0 + 8) * HID + c) =
                            make_float2(acc[mt][nt][2], acc[mt][nt][3]);
                }
            }
        }
    }
}

// ---------------------------------------------------------------------------
// Kernel 2: R12 structure + permuted-P gather (uint4)
// ---------------------------------------------------------------------------
#define OFF_E    0        // 128 x 72 fp16 = 18432
#define OFF_EO   18432    // e_out buffer   = 18432
#define OFF_W1   36864
#define OFF_W2   46080
#define OFF_W3   55296
#define OFF_HN   64512    // 16 x 72 fp16 (rows 8..15 stay zero)
#define OFF_LOG  66816    // 128 floats
#define OFF_TAU  67328
#define OFF_AMX  67360
#define OFF_V    67392
#define OFF_BE   67648
#define OFF_BO   67904
#define OFF_BN   68160
#define OFF_SRC  68416
#define OFF_C    68928
#define FS_SMEM  68944

__global__ __launch_bounds__(256, 2)
void k_fusedT(const float* __restrict__ ef,
              const int*   __restrict__ src_idx,
              const float* __restrict__ We,  const float* __restrict__ be,
              const float* __restrict__ Wa,  const float* __restrict__ ba,
              const float* __restrict__ wa,
              const float* __restrict__ Wo,  const float* __restrict__ bo,
              const float* __restrict__ Wn,  const float* __restrict__ bn,
              float* __restrict__ out)
{
    extern __shared__ char smc[];
    const int tid = threadIdx.x, lane = tid & 31, wid = tid >> 5;
    const int mrow = (wid & 3) * 32, ncol = (wid >> 2) * 32;

    float* sLog = (float*)(smc + OFF_LOG);
    float* sTau = (float*)(smc + OFF_TAU);
    float* sAmx = (float*)(smc + OFF_AMX);
    float* sV   = (float*)(smc + OFF_V);
    float* sBe  = (float*)(smc + OFF_BE);
    float* sBo  = (float*)(smc + OFF_BO);
    float* sBn  = (float*)(smc + OFF_BN);
    int*   sSrc = (int*)  (smc + OFF_SRC);

    for (int i = tid; i < 4096; i += 256) {
        const int n = i >> 6, k = i & 63;
        ((__half*)(smc + OFF_W1))[n * 72 + k] = __float2half(We[k * 64 + n]);
        ((__half*)(smc + OFF_W2))[n * 72 + k] = __float2half(Wo[(NODE_IN + k) * 64 + n]);
        ((__half*)(smc + OFF_W3))[n * 72 + k] = __float2half(Wn[(NODE_IN + k) * 64 + n]);
    }
    for (int i = tid; i < 288; i += 256)
        ((uint32_t*)(smc + OFF_HN + 1152))[i] = 0;
    if (tid < 64) {
        sBe[tid] = be[tid]; sBo[tid] = bo[tid]; sBn[tid] = bn[tid];
        float sv = 0.f;
        #pragma unroll 8
        for (int k = 0; k < 64; k++) sv = fmaf(Wa[tid * 64 + k], wa[k], sv);
        sV[tid] = sv;
    }
    if (tid == 64) {
        float sc = 0.f;
        for (int k = 0; k < 64; k++) sc = fmaf(ba[k], wa[k], sc);
        *(float*)(smc + OFF_C) = sc;
    }
    __syncthreads();
    const float cval = *(const float*)(smc + OFF_C);

    const uint32_t eS  = smem_u32(smc + OFF_E);
    const uint32_t eoS = smem_u32(smc + OFF_EO);
    const uint32_t w1 = smem_u32(smc + OFF_W1), w2 = smem_u32(smc + OFF_W2);
    const uint32_t w3 = smem_u32(smc + OFF_W3);
    const uint32_t hnS = smem_u32(smc + OFF_HN);

    // hoist GEMM3 B fragments (loop-invariant)
    uint32_t b3[2][4];
    {
        const int nc = wid * 8;
        #pragma unroll
        for (int g = 0; g < 2; g++) {
            const uint32_t off = (uint32_t)(((nc + (lane & 7)) * 72 + (lane >> 3) * 8 + g * 32) * 2);
            ldsm4(b3[g], w3 + off);
        }
    }

    // -------- edge-tile prefetch (registers) --------
    int tile = blockIdx.x;
    float4 ev[8];
    int srcv = 0;
    if (tile < NTILE) {
        const float4* eg = (const float4*)(ef + (size_t)tile * 8192);
        #pragma unroll
        for (int t = 0; t < 4; t++) {
            const int idx = tid + 256 * t;
            const int r = idx >> 3, c8 = idx & 7;
            ev[2 * t]     = eg[r * 16 + c8 * 2];
            ev[2 * t + 1] = eg[r * 16 + c8 * 2 + 1];
        }
        if (tid < 128) srcv = src_idx[tile * 128 + tid];
    }

    for (; tile < NTILE; tile += gridDim.x) {
        // ---- staging from REGISTERS -> fp16 smem + fused logits ----
        #pragma unroll
        for (int t = 0; t < 4; t++) {
            const int idx = tid + 256 * t;
            const int r = idx >> 3, c8 = idx & 7;
            const float4 v0 = ev[2 * t];
            const float4 v1 = ev[2 * t + 1];
            uint4 pk;
            pk.x = h2u(__floats2half2_rn(v0.x, v0.y));
            pk.y = h2u(__floats2half2_rn(v0.z, v0.w));
            pk.z = h2u(__floats2half2_rn(v1.x, v1.y));
            pk.w = h2u(__floats2half2_rn(v1.z, v1.w));
            *(uint4*)(smc + OFF_E + (size_t)r * 144 + c8 * 16) = pk;
            const float* vv = sV + c8 * 8;
            float p = v0.x * vv[0] + v0.y * vv[1] + v0.z * vv[2] + v0.w * vv[3]
                    + v1.x * vv[4] + v1.y * vv[5] + v1.z * vv[6] + v1.w * vv[7];
            p += __shfl_xor_sync(0xffffffffu, p, 1);
            p += __shfl_xor_sync(0xffffffffu, p, 2);
            p += __shfl_xor_sync(0xffffffffu, p, 4);
            if ((tid & 7) == 0) sLog[r] = p;
        }
        if (tid < 128) sSrc[tid] = srcv;
        __syncthreads();   // S1: E + logits + src visible

        // ---- sparsemax (8 threads of warp 0) ----
        if (tid < 8) {
            float z[16], amax = -3.4e38f;
            #pragma unroll
            for (int d = 0; d < 16; d++) {
                float raw = sLog[tid * 16 + d] + cval;
                raw = (raw > 0.f) ? raw : 0.01f * raw;
                sLog[tid * 16 + d] = raw;
                z[d] = raw; amax = fmaxf(amax, z[d]);
            }
            #pragma unroll
            for (int d = 0; d < 16; d++) z[d] -= amax;
            #pragma unroll
            for (int kk2 = 2; kk2 <= 16; kk2 <<= 1)
                #pragma unroll
                for (int j = kk2 >> 1; j > 0; j >>= 1)
                    #pragma unroll
                    for (int i = 0; i < 16; i++) {
                        const int l = i ^ j;
                        if (l > i) {
                            const bool up = ((i & kk2) == 0);
                            const float a0 = z[i], b0 = z[l];
                            if (up ? (a0 > b0) : (a0 < b0)) { z[i] = b0; z[l] = a0; }
                        }
                    }
            float cs = 0.f, cssel = 0.f, kk = 1.f;
            #pragma unroll
            for (int j = 1; j <= 16; j++) {
                const float zz = z[16 - j];
                cs += zz;
                if (1.f + (float)j * zz > cs) { kk = (float)j; cssel = cs; }
            }
            sTau[tid] = (cssel - 1.f) / kk;
            sAmx[tid] = amax;
        }

        // ---- P-row prefetch: permuted layout -> ONE uint4 per row ----
        uint4 pq0[2], pq1[2];
        {
            const int po = ncol + 8 * (lane & 3);
            #pragma unroll
            for (int mt = 0; mt < 2; mt++) {
                const int r0 = mrow + mt * 16 + (lane >> 2);
                pq0[mt] = *(const uint4*)(g_P + (size_t)sSrc[r0] * HID + po);
                pq1[mt] = *(const uint4*)(g_P + (size_t)sSrc[r0 + 8] * HID + po);
            }
        }

        float acc[2][4][4];

        // ---- GEMM1: e_out_pre = E @ We^T ----
        #pragma unroll
        for (int a = 0; a < 2; a++)
            #pragma unroll
            for (int b = 0; b < 4; b++)
                #pragma unroll
                for (int c = 0; c < 4; c++) acc[a][b][c] = 0.f;
        gemm_1p<4, 72>(eS, w1, mrow, ncol, lane, acc);

        // ---- epilogue1: relu(+be) -> e_out buffer ----
        #pragma unroll
        for (int mt = 0; mt < 2; mt++) {
            const int r0 = mrow + mt * 16 + (lane >> 2);
            #pragma unroll
            for (int nt = 0; nt < 4; nt++) {
                const int c = ncol + nt * 8 + (lane & 3) * 2;
                const float x0 = fmaxf(acc[mt][nt][0] + sBe[c],     0.f);
                const float x1 = fmaxf(acc[mt][nt][1] + sBe[c + 1], 0.f);
                const float x2 = fmaxf(acc[mt][nt][2] + sBe[c],     0.f);
                const float x3 = fmaxf(acc[mt][nt][3] + sBe[c + 1], 0.f);
                *(uint32_t*)(smc + OFF_EO + (size_t)(r0 * 72 + c) * 2) =
                    h2u(__floats2half2_rn(x0, x1));
                *(uint32_t*)(smc + OFF_EO + (size_t)((r0 + 8) * 72 + c) * 2) =
                    h2u(__floats2half2_rn(x2, x3));
            }
        }
        __syncthreads();   // S2: e_out + tau visible

        // ---- GEMM2: m_pre = e_out @ Wo_bot^T ----
        #pragma unroll
        for (int a = 0; a < 2; a++)
            #pragma unroll
            for (int b = 0; b < 4; b++)
                #pragma unroll
                for (int c = 0; c < 4; c++) acc[a][b][c] = 0.f;
        gemm_1p<4, 72>(eoS, w2, mrow, ncol, lane, acc);

        // ---- epilogue2: m = relu(acc + P + bo); alpha-weighted sum -> HN ----
        #pragma unroll
        for (int mt = 0; mt < 2; mt++) {
            const int ln = (mrow >> 4) + mt;
            const int r0 = mrow + mt * 16 + (lane >> 2);
            const int r1 = r0 + 8;
            const float at = sAmx[ln] + sTau[ln];
            const float al0 = fmaxf(sLog[r0] - at, 0.f);
            const float al1 = fmaxf(sLog[r1] - at, 0.f);
            const uint32_t* q0 = (const uint32_t*)&pq0[mt];
            const uint32_t* q1 = (const uint32_t*)&pq1[mt];
            #pragma unroll
            for (int nt = 0; nt < 4; nt++) {
                const int c = ncol + nt * 8 + (lane & 3) * 2;
                const float2 p0 = __half22float2(*(const __half2*)&q0[nt]);
                const float2 p1 = __half22float2(*(const __half2*)&q1[nt]);
                const float m00 = fmaxf(acc[mt][nt][0] + p0.x + sBo[c],     0.f);
                const float m01 = fmaxf(acc[mt][nt][1] + p0.y + sBo[c + 1], 0.f);
                const float m10 = fmaxf(acc[mt][nt][2] + p1.x + sBo[c],     0.f);
                const float m11 = fmaxf(acc[mt][nt][3] + p1.y + sBo[c + 1], 0.f);
                float sx = m00 * al0 + m10 * al1;
                float sy = m01 * al0 + m11 * al1;
                sx += __shfl_xor_sync(0xffffffffu, sx, 4);
                sy += __shfl_xor_sync(0xffffffffu, sy, 4);
                sx += __shfl_xor_sync(0xffffffffu, sx, 8);
                sy += __shfl_xor_sync(0xffffffffu, sy, 8);
                sx += __shfl_xor_sync(0xffffffffu, sx, 16);
                sy += __shfl_xor_sync(0xffffffffu, sy, 16);
                if (lane < 4)
                    *(uint32_t*)(smc + OFF_HN + (size_t)(ln * 72 + c) * 2) =
                        h2u(__floats2half2_rn(sx, sy));
            }
        }
        __syncthreads();   // S3: HN visible

        // ---- prefetch NEXT tile (overlaps GEMM3 + out stores) ----
        {
            const int tnext = tile + gridDim.x;
            if (tnext < NTILE) {
                const float4* eg = (const float4*)(ef + (size_t)tnext * 8192);
                #pragma unroll
                for (int t = 0; t < 4; t++) {
                    const int idx = tid + 256 * t;
                    const int r = idx >> 3, c8 = idx & 7;
                    ev[2 * t]     = eg[r * 16 + c8 * 2];
                    ev[2 * t + 1] = eg[r * 16 + c8 * 2 + 1];
                }
                if (tid < 128) srcv = src_idx[tnext * 128 + tid];
            }
        }

        // ---- GEMM3 (M=16 padded, 1-pass): out = relu(R + HN @ Wn_bot^T + bn) ----
        {
            float acc3[4] = {0.f, 0.f, 0.f, 0.f};
            #pragma unroll
            for (int ks = 0; ks < 4; ks++) {
                uint32_t a3[4];
                const uint32_t aoff = (uint32_t)(((lane & 15) * 72 + ks * 16 + (lane >> 4) * 8) * 2);
                ldsm4(a3, hnS + aoff);
                const int g = ks >> 1, pr = (ks & 1) * 2;
                mma_f16(acc3, a3, b3[g][pr], b3[g][pr + 1]);
            }
            const int node = tile * 8 + (lane >> 2);
            const int col = wid * 8 + (lane & 3) * 2;
            const float2 r2 = *(const float2*)(g_R + (size_t)node * HID + col);
            const float o0 = acc3[0] + r2.x + sBn[col];
            const float o1 = acc3[1] + r2.y + sBn[col + 1];
            *(float2*)(out + (size_t)node * HID + col) =
                make_float2(fmaxf(o0, 0.f), fmaxf(o1, 0.f));
        }
        // no trailing sync (same hazard argument as R9/R12)
    }
}

// ---------------------------------------------------------------------------
extern "C" void kernel_launch(void* const* d_in, const int* in_sizes, int n_in,
                              void* d_out, int out_size)
{
    const float* nf = (const float*)d_in[0];
    const float* ef = (const float*)d_in[1];
    const int*   si = (const int*)  d_in[2];
    const float* We = (const float*)d_in[3];
    const float* be = (const float*)d_in[4];
    const float* Wa = (const float*)d_in[5];
    const float* ba = (const float*)d_in[6];
    const float* wa = (const float*)d_in[7];
    const float* Wo = (const float*)d_in[8];
    const float* bo = (const float*)d_in[9];
    const float* Wn = (const float*)d_in[10];
    const float* bn = (const float*)d_in[11];
    float* out = (float*)d_out;

    cudaFuncSetAttribute(k_projT,  cudaFuncAttributeMaxDynamicSharedMemorySize, PJ_SMEM);
    cudaFuncSetAttribute(k_fusedT, cudaFuncAttributeMaxDynamicSharedMemorySize, FS_SMEM);

    k_projT<<<PJ_BLOCKS, 256, PJ_SMEM>>>(nf, Wo, Wn);
    k_fusedT<<<296, 256, FS_SMEM>>>(ef, si, We, be, Wa, ba, wa, Wo, bo, Wn, bn, out);
}